// round 3
// baseline (speedup 1.0000x reference)
#include <cuda_runtime.h>
#include <math_constants.h>

// MaxPlusDense: out[b,u] = max( max_i (x[b,i] - kernel[i,u]), bias[u] )
// B=256, D=1024, U=1024, fp32.
//
// Strategy: tropical GEMM with packed add.rn.f32x2 (negated W in smem),
// 8x4 per-thread microtile (1.5 LDS-bytes/cell), split-K=4 to keep 128 CTAs
// with fat 256-thread blocks.

#define B_DIM 256
#define D_DIM 1024
#define U_DIM 1024

#define SPLITS 4
#define KSEG   (D_DIM / SPLITS)   // 256
#define BM 128
#define BN 64
#define BK 16
#define NT 256

// partial results per split (allocation-free scratch)
__device__ float g_scratch[SPLITS][B_DIM * U_DIM];   // 4 MB

__device__ __forceinline__ unsigned long long pack2(float v) {
    unsigned long long r;
    asm("mov.b64 %0, {%1, %1};" : "=l"(r) : "f"(v));
    return r;
}
__device__ __forceinline__ unsigned long long add2(unsigned long long a,
                                                   unsigned long long b) {
    unsigned long long r;
    asm("add.rn.f32x2 %0, %1, %2;" : "=l"(r) : "l"(a), "l"(b));
    return r;
}

__global__ __launch_bounds__(NT, 1) void maxplus_phase1(
    const float* __restrict__ X,   // (B, D)
    const float* __restrict__ W)   // (D, U)
{
    __shared__ float xs[BK][BM];    // x tile, transposed: xs[k][m]
    __shared__ float nks[BK][BN];   // NEGATED kernel tile: nks[k][n] = -W[k][n]

    const int tid   = threadIdx.x;
    const int bn    = blockIdx.x * BN;
    const int bm    = blockIdx.y * BM;
    const int split = blockIdx.z;
    const int kbase = split * KSEG;

    // microtile: 8 rows (m), 4 cols (n)
    const int tm = (tid & 15) * 8;    // 0..120
    const int tn = (tid >> 4) * 4;    // 0..60

    // gmem->smem mapping
    const int xr = tid >> 1;          // 0..127 (m)
    const int xc = (tid & 1) * 8;     // 0 or 8 (k)
    const int kr = tid >> 4;          // 0..15  (k)
    const int kc = (tid & 15) * 4;    // 0..60  (n)

    const float* xg = X + (size_t)(bm + xr) * D_DIM + kbase + xc;
    const float* wg = W + (size_t)(kbase + kr) * U_DIM + bn + kc;

    float acc[8][4];
#pragma unroll
    for (int i = 0; i < 8; i++)
#pragma unroll
        for (int j = 0; j < 4; j++) acc[i][j] = -CUDART_INF_F;

    // prologue: stage first tile in registers
    float4 xv0 = *(const float4*)(xg);
    float4 xv1 = *(const float4*)(xg + 4);
    float4 wv  = *(const float4*)(wg);

#pragma unroll 1
    for (int t = 0; t < KSEG / BK; t++) {
        // commit staged regs to smem (negate W here)
        xs[xc + 0][xr] = xv0.x;
        xs[xc + 1][xr] = xv0.y;
        xs[xc + 2][xr] = xv0.z;
        xs[xc + 3][xr] = xv0.w;
        xs[xc + 4][xr] = xv1.x;
        xs[xc + 5][xr] = xv1.y;
        xs[xc + 6][xr] = xv1.z;
        xs[xc + 7][xr] = xv1.w;
        *(float4*)&nks[kr][kc] = make_float4(-wv.x, -wv.y, -wv.z, -wv.w);
        __syncthreads();

        // prefetch next tile (L2-resident)
        if (t + 1 < KSEG / BK) {
            xv0 = *(const float4*)(xg + (t + 1) * BK);
            xv1 = *(const float4*)(xg + (t + 1) * BK + 4);
            wv  = *(const float4*)(wg + (size_t)(t + 1) * BK * U_DIM);
        }

#pragma unroll
        for (int kk = 0; kk < BK; kk++) {
            // 8 consecutive m-values as 4 aligned f32x2 pairs
            ulonglong2 A0 = *(const ulonglong2*)&xs[kk][tm];
            ulonglong2 A1 = *(const ulonglong2*)&xs[kk][tm + 4];
            float4 b = *(const float4*)&nks[kk][tn];

            unsigned long long ap[4] = {A0.x, A0.y, A1.x, A1.y};
            unsigned long long bb[4] = {pack2(b.x), pack2(b.y), pack2(b.z), pack2(b.w)};

#pragma unroll
            for (int j = 0; j < 4; j++) {
#pragma unroll
                for (int p = 0; p < 4; p++) {
                    unsigned long long tt = add2(ap[p], bb[j]);
                    float lo, hi;
                    asm("mov.b64 {%0, %1}, %2;" : "=f"(lo), "=f"(hi) : "l"(tt));
                    acc[2 * p    ][j] = fmaxf(acc[2 * p    ][j], lo);
                    acc[2 * p + 1][j] = fmaxf(acc[2 * p + 1][j], hi);
                }
            }
        }
        __syncthreads();
    }

    // write partials (no bias here)
    float* dst = g_scratch[split];
#pragma unroll
    for (int i = 0; i < 8; i++) {
        float4 o = make_float4(acc[i][0], acc[i][1], acc[i][2], acc[i][3]);
        *(float4*)&dst[(size_t)(bm + tm + i) * U_DIM + bn + tn] = o;
    }
}

__global__ __launch_bounds__(256, 1) void maxplus_combine(
    const float* __restrict__ bias,
    float* __restrict__ out)
{
    const int idx = blockIdx.x * blockDim.x + threadIdx.x;   // 0..65535 (float4 units)
    float4 b  = ((const float4*)bias)[idx & (U_DIM / 4 - 1)];
    float4 s0 = ((const float4*)g_scratch[0])[idx];
    float4 s1 = ((const float4*)g_scratch[1])[idx];
    float4 s2 = ((const float4*)g_scratch[2])[idx];
    float4 s3 = ((const float4*)g_scratch[3])[idx];
    float4 o;
    o.x = fmaxf(fmaxf(fmaxf(s0.x, s1.x), fmaxf(s2.x, s3.x)), b.x);
    o.y = fmaxf(fmaxf(fmaxf(s0.y, s1.y), fmaxf(s2.y, s3.y)), b.y);
    o.z = fmaxf(fmaxf(fmaxf(s0.z, s1.z), fmaxf(s2.z, s3.z)), b.z);
    o.w = fmaxf(fmaxf(fmaxf(s0.w, s1.w), fmaxf(s2.w, s3.w)), b.w);
    ((float4*)out)[idx] = o;
}

extern "C" void kernel_launch(void* const* d_in, const int* in_sizes, int n_in,
                              void* d_out, int out_size)
{
    const float* x      = (const float*)d_in[0];   // (256, 1024)
    const float* kernel = (const float*)d_in[1];   // (1024, 1024)
    const float* bias   = (const float*)d_in[2];   // (1024,)
    float* out          = (float*)d_out;           // (256, 1024)

    dim3 grid1(U_DIM / BN, B_DIM / BM, SPLITS);    // (16, 2, 4) = 128 CTAs
    maxplus_phase1<<<grid1, NT>>>(x, kernel);

    const int n4 = (B_DIM * U_DIM) / 4;            // 65536
    maxplus_combine<<<n4 / 256, 256>>>(bias, out);
}

// round 4
// speedup vs baseline: 1.0107x; 1.0107x over previous
#include <cuda_runtime.h>
#include <math_constants.h>

// MaxPlusDense: out[b,u] = max( max_i (x[b,i] - kernel[i,u]), bias[u] )
// B=256, D=1024, U=1024, fp32.
//
// Strategy: tropical GEMM with packed add.rn.f32x2 (negated W in smem),
// 8x4 per-thread microtile (1.5 LDS-bytes/cell), split-K=4 to keep 128 CTAs
// with fat 256-thread blocks.

#define B_DIM 256
#define D_DIM 1024
#define U_DIM 1024

#define SPLITS 4
#define KSEG   (D_DIM / SPLITS)   // 256
#define BM 128
#define BN 64
#define BK 16
#define NT 256

// partial results per split (allocation-free scratch)
__device__ float g_scratch[SPLITS][B_DIM * U_DIM];   // 4 MB

__device__ __forceinline__ unsigned long long pack2(float v) {
    unsigned long long r;
    asm("mov.b64 %0, {%1, %1};" : "=l"(r) : "f"(v));
    return r;
}
__device__ __forceinline__ unsigned long long add2(unsigned long long a,
                                                   unsigned long long b) {
    unsigned long long r;
    asm("add.rn.f32x2 %0, %1, %2;" : "=l"(r) : "l"(a), "l"(b));
    return r;
}

__global__ __launch_bounds__(NT, 1) void maxplus_phase1(
    const float* __restrict__ X,   // (B, D)
    const float* __restrict__ W)   // (D, U)
{
    __shared__ float xs[BK][BM];    // x tile, transposed: xs[k][m]
    __shared__ float nks[BK][BN];   // NEGATED kernel tile: nks[k][n] = -W[k][n]

    const int tid   = threadIdx.x;
    const int bn    = blockIdx.x * BN;
    const int bm    = blockIdx.y * BM;
    const int split = blockIdx.z;
    const int kbase = split * KSEG;

    // microtile: 8 rows (m), 4 cols (n)
    const int tm = (tid & 15) * 8;    // 0..120
    const int tn = (tid >> 4) * 4;    // 0..60

    // gmem->smem mapping
    const int xr = tid >> 1;          // 0..127 (m)
    const int xc = (tid & 1) * 8;     // 0 or 8 (k)
    const int kr = tid >> 4;          // 0..15  (k)
    const int kc = (tid & 15) * 4;    // 0..60  (n)

    const float* xg = X + (size_t)(bm + xr) * D_DIM + kbase + xc;
    const float* wg = W + (size_t)(kbase + kr) * U_DIM + bn + kc;

    float acc[8][4];
#pragma unroll
    for (int i = 0; i < 8; i++)
#pragma unroll
        for (int j = 0; j < 4; j++) acc[i][j] = -CUDART_INF_F;

    // prologue: stage first tile in registers
    float4 xv0 = *(const float4*)(xg);
    float4 xv1 = *(const float4*)(xg + 4);
    float4 wv  = *(const float4*)(wg);

#pragma unroll 1
    for (int t = 0; t < KSEG / BK; t++) {
        // commit staged regs to smem (negate W here)
        xs[xc + 0][xr] = xv0.x;
        xs[xc + 1][xr] = xv0.y;
        xs[xc + 2][xr] = xv0.z;
        xs[xc + 3][xr] = xv0.w;
        xs[xc + 4][xr] = xv1.x;
        xs[xc + 5][xr] = xv1.y;
        xs[xc + 6][xr] = xv1.z;
        xs[xc + 7][xr] = xv1.w;
        *(float4*)&nks[kr][kc] = make_float4(-wv.x, -wv.y, -wv.z, -wv.w);
        __syncthreads();

        // prefetch next tile (L2-resident)
        if (t + 1 < KSEG / BK) {
            xv0 = *(const float4*)(xg + (t + 1) * BK);
            xv1 = *(const float4*)(xg + (t + 1) * BK + 4);
            wv  = *(const float4*)(wg + (size_t)(t + 1) * BK * U_DIM);
        }

#pragma unroll
        for (int kk = 0; kk < BK; kk++) {
            // 8 consecutive m-values as 4 aligned f32x2 pairs
            ulonglong2 A0 = *(const ulonglong2*)&xs[kk][tm];
            ulonglong2 A1 = *(const ulonglong2*)&xs[kk][tm + 4];
            float4 b = *(const float4*)&nks[kk][tn];

            unsigned long long ap[4] = {A0.x, A0.y, A1.x, A1.y};
            unsigned long long bb[4] = {pack2(b.x), pack2(b.y), pack2(b.z), pack2(b.w)};

#pragma unroll
            for (int j = 0; j < 4; j++) {
#pragma unroll
                for (int p = 0; p < 4; p++) {
                    unsigned long long tt = add2(ap[p], bb[j]);
                    float lo, hi;
                    asm("mov.b64 {%0, %1}, %2;" : "=f"(lo), "=f"(hi) : "l"(tt));
                    acc[2 * p    ][j] = fmaxf(acc[2 * p    ][j], lo);
                    acc[2 * p + 1][j] = fmaxf(acc[2 * p + 1][j], hi);
                }
            }
        }
        __syncthreads();
    }

    // write partials (no bias here)
    float* dst = g_scratch[split];
#pragma unroll
    for (int i = 0; i < 8; i++) {
        float4 o = make_float4(acc[i][0], acc[i][1], acc[i][2], acc[i][3]);
        *(float4*)&dst[(size_t)(bm + tm + i) * U_DIM + bn + tn] = o;
    }
}

__global__ __launch_bounds__(256, 1) void maxplus_combine(
    const float* __restrict__ bias,
    float* __restrict__ out)
{
    const int idx = blockIdx.x * blockDim.x + threadIdx.x;   // 0..65535 (float4 units)
    float4 b  = ((const float4*)bias)[idx & (U_DIM / 4 - 1)];
    float4 s0 = ((const float4*)g_scratch[0])[idx];
    float4 s1 = ((const float4*)g_scratch[1])[idx];
    float4 s2 = ((const float4*)g_scratch[2])[idx];
    float4 s3 = ((const float4*)g_scratch[3])[idx];
    float4 o;
    o.x = fmaxf(fmaxf(fmaxf(s0.x, s1.x), fmaxf(s2.x, s3.x)), b.x);
    o.y = fmaxf(fmaxf(fmaxf(s0.y, s1.y), fmaxf(s2.y, s3.y)), b.y);
    o.z = fmaxf(fmaxf(fmaxf(s0.z, s1.z), fmaxf(s2.z, s3.z)), b.z);
    o.w = fmaxf(fmaxf(fmaxf(s0.w, s1.w), fmaxf(s2.w, s3.w)), b.w);
    ((float4*)out)[idx] = o;
}

extern "C" void kernel_launch(void* const* d_in, const int* in_sizes, int n_in,
                              void* d_out, int out_size)
{
    const float* x      = (const float*)d_in[0];   // (256, 1024)
    const float* kernel = (const float*)d_in[1];   // (1024, 1024)
    const float* bias   = (const float*)d_in[2];   // (1024,)
    float* out          = (float*)d_out;           // (256, 1024)

    dim3 grid1(U_DIM / BN, B_DIM / BM, SPLITS);    // (16, 2, 4) = 128 CTAs
    maxplus_phase1<<<grid1, NT>>>(x, kernel);

    const int n4 = (B_DIM * U_DIM) / 4;            // 65536
    maxplus_combine<<<n4 / 256, 256>>>(bias, out);
}

// round 5
// speedup vs baseline: 1.0176x; 1.0068x over previous
#include <cuda_runtime.h>
#include <math_constants.h>

// MaxPlusDense: out[b,u] = max( max_i (x[b,i] - kernel[i,u]), bias[u] )
// B=256, D=1024, U=1024, fp32.
//
// Strategy: tropical GEMM with packed add.rn.f32x2 (negated W in smem),
// 8x4 per-thread microtile (1.5 LDS-bytes/cell), split-K=4 to keep 128 CTAs
// with fat 256-thread blocks.

#define B_DIM 256
#define D_DIM 1024
#define U_DIM 1024

#define SPLITS 4
#define KSEG   (D_DIM / SPLITS)   // 256
#define BM 128
#define BN 64
#define BK 16
#define NT 256

// partial results per split (allocation-free scratch)
__device__ float g_scratch[SPLITS][B_DIM * U_DIM];   // 4 MB

__device__ __forceinline__ unsigned long long pack2(float v) {
    unsigned long long r;
    asm("mov.b64 %0, {%1, %1};" : "=l"(r) : "f"(v));
    return r;
}
__device__ __forceinline__ unsigned long long add2(unsigned long long a,
                                                   unsigned long long b) {
    unsigned long long r;
    asm("add.rn.f32x2 %0, %1, %2;" : "=l"(r) : "l"(a), "l"(b));
    return r;
}

__global__ __launch_bounds__(NT, 1) void maxplus_phase1(
    const float* __restrict__ X,   // (B, D)
    const float* __restrict__ W)   // (D, U)
{
    __shared__ float xs[BK][BM];    // x tile, transposed: xs[k][m]
    __shared__ float nks[BK][BN];   // NEGATED kernel tile: nks[k][n] = -W[k][n]

    const int tid   = threadIdx.x;
    const int bn    = blockIdx.x * BN;
    const int bm    = blockIdx.y * BM;
    const int split = blockIdx.z;
    const int kbase = split * KSEG;

    // microtile: 8 rows (m), 4 cols (n)
    const int tm = (tid & 15) * 8;    // 0..120
    const int tn = (tid >> 4) * 4;    // 0..60

    // gmem->smem mapping
    const int xr = tid >> 1;          // 0..127 (m)
    const int xc = (tid & 1) * 8;     // 0 or 8 (k)
    const int kr = tid >> 4;          // 0..15  (k)
    const int kc = (tid & 15) * 4;    // 0..60  (n)

    const float* xg = X + (size_t)(bm + xr) * D_DIM + kbase + xc;
    const float* wg = W + (size_t)(kbase + kr) * U_DIM + bn + kc;

    float acc[8][4];
#pragma unroll
    for (int i = 0; i < 8; i++)
#pragma unroll
        for (int j = 0; j < 4; j++) acc[i][j] = -CUDART_INF_F;

    // prologue: stage first tile in registers
    float4 xv0 = *(const float4*)(xg);
    float4 xv1 = *(const float4*)(xg + 4);
    float4 wv  = *(const float4*)(wg);

#pragma unroll 1
    for (int t = 0; t < KSEG / BK; t++) {
        // commit staged regs to smem (negate W here)
        xs[xc + 0][xr] = xv0.x;
        xs[xc + 1][xr] = xv0.y;
        xs[xc + 2][xr] = xv0.z;
        xs[xc + 3][xr] = xv0.w;
        xs[xc + 4][xr] = xv1.x;
        xs[xc + 5][xr] = xv1.y;
        xs[xc + 6][xr] = xv1.z;
        xs[xc + 7][xr] = xv1.w;
        *(float4*)&nks[kr][kc] = make_float4(-wv.x, -wv.y, -wv.z, -wv.w);
        __syncthreads();

        // prefetch next tile (L2-resident)
        if (t + 1 < KSEG / BK) {
            xv0 = *(const float4*)(xg + (t + 1) * BK);
            xv1 = *(const float4*)(xg + (t + 1) * BK + 4);
            wv  = *(const float4*)(wg + (size_t)(t + 1) * BK * U_DIM);
        }

#pragma unroll
        for (int kk = 0; kk < BK; kk++) {
            // 8 consecutive m-values as 4 aligned f32x2 pairs
            ulonglong2 A0 = *(const ulonglong2*)&xs[kk][tm];
            ulonglong2 A1 = *(const ulonglong2*)&xs[kk][tm + 4];
            float4 b = *(const float4*)&nks[kk][tn];

            unsigned long long ap[4] = {A0.x, A0.y, A1.x, A1.y};
            unsigned long long bb[4] = {pack2(b.x), pack2(b.y), pack2(b.z), pack2(b.w)};

#pragma unroll
            for (int j = 0; j < 4; j++) {
#pragma unroll
                for (int p = 0; p < 4; p++) {
                    unsigned long long tt = add2(ap[p], bb[j]);
                    float lo, hi;
                    asm("mov.b64 {%0, %1}, %2;" : "=f"(lo), "=f"(hi) : "l"(tt));
                    acc[2 * p    ][j] = fmaxf(acc[2 * p    ][j], lo);
                    acc[2 * p + 1][j] = fmaxf(acc[2 * p + 1][j], hi);
                }
            }
        }
        __syncthreads();
    }

    // write partials (no bias here)
    float* dst = g_scratch[split];
#pragma unroll
    for (int i = 0; i < 8; i++) {
        float4 o = make_float4(acc[i][0], acc[i][1], acc[i][2], acc[i][3]);
        *(float4*)&dst[(size_t)(bm + tm + i) * U_DIM + bn + tn] = o;
    }
}

__global__ __launch_bounds__(256, 1) void maxplus_combine(
    const float* __restrict__ bias,
    float* __restrict__ out)
{
    const int idx = blockIdx.x * blockDim.x + threadIdx.x;   // 0..65535 (float4 units)
    float4 b  = ((const float4*)bias)[idx & (U_DIM / 4 - 1)];
    float4 s0 = ((const float4*)g_scratch[0])[idx];
    float4 s1 = ((const float4*)g_scratch[1])[idx];
    float4 s2 = ((const float4*)g_scratch[2])[idx];
    float4 s3 = ((const float4*)g_scratch[3])[idx];
    float4 o;
    o.x = fmaxf(fmaxf(fmaxf(s0.x, s1.x), fmaxf(s2.x, s3.x)), b.x);
    o.y = fmaxf(fmaxf(fmaxf(s0.y, s1.y), fmaxf(s2.y, s3.y)), b.y);
    o.z = fmaxf(fmaxf(fmaxf(s0.z, s1.z), fmaxf(s2.z, s3.z)), b.z);
    o.w = fmaxf(fmaxf(fmaxf(s0.w, s1.w), fmaxf(s2.w, s3.w)), b.w);
    ((float4*)out)[idx] = o;
}

extern "C" void kernel_launch(void* const* d_in, const int* in_sizes, int n_in,
                              void* d_out, int out_size)
{
    const float* x      = (const float*)d_in[0];   // (256, 1024)
    const float* kernel = (const float*)d_in[1];   // (1024, 1024)
    const float* bias   = (const float*)d_in[2];   // (1024,)
    float* out          = (float*)d_out;           // (256, 1024)

    dim3 grid1(U_DIM / BN, B_DIM / BM, SPLITS);    // (16, 2, 4) = 128 CTAs
    maxplus_phase1<<<grid1, NT>>>(x, kernel);

    const int n4 = (B_DIM * U_DIM) / 4;            // 65536
    maxplus_combine<<<n4 / 256, 256>>>(bias, out);
}